// round 13
// baseline (speedup 1.0000x reference)
#include <cuda_runtime.h>
#include <cuda_fp16.h>
#include <math.h>
#include <stdint.h>

#define SEQ    2048
#define BATCH  4
#define KCTX   3
#define EMBED  512
#define HIDDEN 256
#define VOCAB  32000
#define MROWS  (SEQ * BATCH)      // 8192
#define K1     (KCTX * EMBED)     // 1536

// ---------------- scratch (static device globals) ----------------
__device__ __half g_flat[MROWS * K1];      // [8192][1536] fp16
__device__ __half g_w1t[HIDDEN * K1];      // [256][1536] K-major fp16
__device__ __half g_w2t[VOCAB * HIDDEN];   // [32000][256] K-major fp16
__device__ __half g_h[MROWS * HIDDEN];     // [8192][256] fp16

// ---------------- helpers ----------------
__device__ __forceinline__ uint32_t smem_u32(const void* p) {
    uint32_t a;
    asm("{ .reg .u64 t; cvta.to.shared.u64 t, %1; cvt.u32.u64 %0, t; }" : "=r"(a) : "l"(p));
    return a;
}
__device__ __forceinline__ void cp16(uint32_t dst, const void* src) {
    asm volatile("cp.async.cg.shared.global [%0], [%1], 16;\n" :: "r"(dst), "l"(src));
}
__device__ __forceinline__ void cp_commit() { asm volatile("cp.async.commit_group;\n" ::: "memory"); }

#define LDSM_X4(r0, r1, r2, r3, addr) \
    asm volatile("ldmatrix.sync.aligned.m8n8.x4.shared.b16 {%0,%1,%2,%3}, [%4];" \
                 : "=r"(r0), "=r"(r1), "=r"(r2), "=r"(r3) : "r"(addr))

#define MMA_F16(d, a, b) \
    asm volatile("mma.sync.aligned.m16n8k16.row.col.f32.f16.f16.f32 " \
                 "{%0,%1,%2,%3}, {%4,%5,%6,%7}, {%8,%9}, {%0,%1,%2,%3};" \
                 : "+f"((d)[0]), "+f"((d)[1]), "+f"((d)[2]), "+f"((d)[3]) \
                 : "r"((a)[0]), "r"((a)[1]), "r"((a)[2]), "r"((a)[3]), \
                   "r"((b)[0]), "r"((b)[1]))

// fp16-accumulate variant: D/C are 2 regs of packed half2
#define MMA_F16H(d, a, b) \
    asm volatile("mma.sync.aligned.m16n8k16.row.col.f16.f16.f16.f16 " \
                 "{%0,%1}, {%2,%3,%4,%5}, {%6,%7}, {%0,%1};" \
                 : "+r"((d)[0]), "+r"((d)[1]) \
                 : "r"((a)[0]), "r"((a)[1]), "r"((a)[2]), "r"((a)[3]), \
                   "r"((b)[0]), "r"((b)[1]))

__device__ __forceinline__ float gelu_exact(float x) {
    return 0.5f * x * (1.0f + erff(x * 0.70710678118654752f));
}

// ---------------------------------------------------------------------------
// Gather -> fp16 flat
// ---------------------------------------------------------------------------
__global__ void gather_f16(const int* __restrict__ tokens, const float* __restrict__ emb) {
    int idx = blockIdx.x * blockDim.x + threadIdx.x;   // one 8-elem chunk
    const int Q = K1 / 8;                               // 192 per row
    if (idx >= MROWS * Q) return;
    int r = idx / Q;
    int q = idx - r * Q;
    int s = r >> 2;
    int b = r & 3;
    int g = q / (EMBED / 8);
    int e8 = q - g * (EMBED / 8);
    int pos = s + g - (KCTX - 1);
    int tok = (pos >= 0) ? tokens[pos * BATCH + b] : 0;
    const float4* src = reinterpret_cast<const float4*>(emb + (size_t)tok * EMBED) + e8 * 2;
    float4 v0 = src[0];
    float4 v1 = src[1];
    struct alignas(16) H8 { __half2 a, b, c, d; } o;
    o.a = __floats2half2_rn(v0.x, v0.y);
    o.b = __floats2half2_rn(v0.z, v0.w);
    o.c = __floats2half2_rn(v1.x, v1.y);
    o.d = __floats2half2_rn(v1.z, v1.w);
    reinterpret_cast<H8*>(g_flat)[idx] = o;
}

// ---------------------------------------------------------------------------
// Transpose + fp16: W[R][C] -> T[C][R]
// ---------------------------------------------------------------------------
__global__ void transpose_f16(const float* __restrict__ W, __half* __restrict__ T,
                              int R, int C) {
    __shared__ float t[32][33];
    int c = blockIdx.x * 32 + threadIdx.x;
    int r = blockIdx.y * 32 + threadIdx.y;
    t[threadIdx.y][threadIdx.x] = W[(size_t)r * C + c];
    __syncthreads();
    int c2 = blockIdx.x * 32 + threadIdx.y;
    int r2 = blockIdx.y * 32 + threadIdx.x;
    T[(size_t)c2 * R + r2] = __float2half_rn(t[threadIdx.x][threadIdx.y]);
}

// ---------------------------------------------------------------------------
// GEMM1 (fp16 HMMA, fp32 accum): h = fp16(gelu(flat @ W1^T + b1))
// BM=64, BN=128, BK=64, 8 warps (2x4), warp 32x32. 3-stage cp.async.
// ---------------------------------------------------------------------------
#define RSB2 144   // 64 halves (128B) + 16B pad

template <int KD, int BMt, int BN_, int WM, int WN>
__global__ void __launch_bounds__(32 * WM * WN, 2)
gemm16(const __half* __restrict__ A, const __half* __restrict__ Bt,
       const float* __restrict__ bias, __half* __restrict__ outp, int N) {
    extern __shared__ char smem[];
    constexpr int NT    = 32 * WM * WN;
    constexpr int WROWS = BMt / WM;
    constexpr int WCOLS = BN_ / WN;
    constexpr int MFR   = WROWS / 16;
    constexpr int NFR   = WCOLS / 8;
    constexpr int ROWS  = BMt + BN_;
    constexpr int STAGE = ROWS * RSB2;
    constexpr int NKB   = KD / 64;
    constexpr int NCP   = ROWS * 8 / NT;

    uint32_t sb = smem_u32(smem);
    int tid = threadIdx.x;
    int wid = tid >> 5;
    int lane = tid & 31;
    int warp_m = wid % WM;
    int warp_n = wid / WM;
    int bm = blockIdx.x * BMt;
    int bn = blockIdx.y * BN_;

    float acc[MFR][NFR][4];
#pragma unroll
    for (int i = 0; i < MFR; i++)
#pragma unroll
        for (int j = 0; j < NFR; j++)
#pragma unroll
            for (int r = 0; r < 4; r++) acc[i][j][r] = 0.0f;

    auto issue = [&](int kb) {
        int s = kb % 3;
        int koff = kb * 64;
        uint32_t base = sb + s * STAGE;
#pragma unroll
        for (int i = 0; i < NCP; i++) {
            int li = tid + i * NT;
            int r = li >> 3;
            int ch = li & 7;
            const __half* src = (r < BMt)
                ? A  + (size_t)(bm + r) * KD + koff + ch * 8
                : Bt + (size_t)(bn + r - BMt) * KD + koff + ch * 8;
            cp16(base + r * RSB2 + ch * 16, src);
        }
        cp_commit();
    };

    issue(0);
    issue(1);

    int lrow = (lane & 7) + ((lane >> 3) & 1) * 8;
    int lkb = (lane >> 4) * 16;
    uint32_t a_off = (uint32_t)(warp_m * WROWS + lrow) * RSB2 + lkb;
    uint32_t b_off = (uint32_t)(BMt + warp_n * WCOLS + lrow) * RSB2 + lkb;

    for (int kb = 0; kb < NKB; kb++) {
        int s = kb % 3;
        asm volatile("cp.async.wait_group 1;\n" ::: "memory");
        __syncthreads();
        if (kb + 2 < NKB) issue(kb + 2);

        uint32_t smA = sb + s * STAGE;
#pragma unroll
        for (int k16 = 0; k16 < 4; k16++) {
            uint32_t ko = k16 * 32;
            uint32_t ar[MFR][4];
#pragma unroll
            for (int fm = 0; fm < MFR; fm++)
                LDSM_X4(ar[fm][0], ar[fm][1], ar[fm][2], ar[fm][3],
                        smA + a_off + fm * 16 * RSB2 + ko);
            uint32_t br[NFR][2];
#pragma unroll
            for (int fp = 0; fp < NFR / 2; fp++) {
                uint32_t r0, r1, r2, r3;
                LDSM_X4(r0, r1, r2, r3,
                        smA + b_off + fp * 16 * RSB2 + ko);
                br[2 * fp][0] = r0; br[2 * fp][1] = r2;
                br[2 * fp + 1][0] = r1; br[2 * fp + 1][1] = r3;
            }
#pragma unroll
            for (int fm = 0; fm < MFR; fm++)
#pragma unroll
                for (int fn = 0; fn < NFR; fn++)
                    MMA_F16(acc[fm][fn], ar[fm], br[fn]);
        }
    }

    int gr = lane >> 2;
    int qc = (lane & 3) * 2;
#pragma unroll
    for (int fm = 0; fm < MFR; fm++) {
        int m0 = bm + warp_m * WROWS + fm * 16 + gr;
#pragma unroll
        for (int fn = 0; fn < NFR; fn++) {
            int c0 = bn + warp_n * WCOLS + fn * 8 + qc;
            float2 bv = *reinterpret_cast<const float2*>(bias + c0);
            *reinterpret_cast<__half2*>(outp + (size_t)m0 * N + c0) =
                __floats2half2_rn(gelu_exact(acc[fm][fn][0] + bv.x),
                                  gelu_exact(acc[fm][fn][1] + bv.y));
            *reinterpret_cast<__half2*>(outp + (size_t)(m0 + 8) * N + c0) =
                __floats2half2_rn(gelu_exact(acc[fm][fn][2] + bv.x),
                                  gelu_exact(acc[fm][fn][3] + bv.y));
        }
    }
}

// ---------------------------------------------------------------------------
// GEMM2 (fp16 ACCUM + per-k-block fp32 promotion):
// logits = h @ W2^T + b2.  M=8192, N=32000, K=256.
// BM=128, BN=128, BK=64, 256 threads (8 warps 2x4), warp tile 64x32.
// acc16 accumulates one k-block (K=64) in fp16, promoted to fp32 master.
// 3-stage cp.async, hoisted addresses.
// ---------------------------------------------------------------------------
#define STGH ((128 + 128) * RSB2)      // 36864
#define SMEM_G2 (3 * STGH)             // 110592

__global__ void __launch_bounds__(256, 1)
gemm2h(const __half* __restrict__ A, const __half* __restrict__ Bt,
       const float* __restrict__ bias, float* __restrict__ out) {
    extern __shared__ char smem[];
    uint32_t sb = smem_u32(smem);
    int tid = threadIdx.x;
    int wid = tid >> 5;
    int lane = tid & 31;
    int warp_m = wid & 1;              // 2 (64 rows each)
    int warp_n = wid >> 1;             // 4 (32 cols each)
    int bm = blockIdx.x * 128;
    int bn = blockIdx.y * 128;

    // hoisted per-thread load addresses
    int lr = tid >> 3;                 // 0..31
    int lc = tid & 7;
    const __half* aptr = A  + (size_t)(bm + lr) * HIDDEN + lc * 8;
    const __half* bptr = Bt + (size_t)(bn + lr) * HIDDEN + lc * 8;
    uint32_t sdst = sb + (uint32_t)lr * RSB2 + lc * 16;

    auto issue = [&](int kb) {
        uint32_t base = sdst + (kb % 3) * STGH;
        int koff = kb * 64;
#pragma unroll
        for (int i = 0; i < 4; i++)    // A rows lr+i*32
            cp16(base + i * 32 * RSB2, aptr + (size_t)i * 32 * HIDDEN + koff);
#pragma unroll
        for (int i = 0; i < 4; i++)    // B rows lr+i*32
            cp16(base + (128 + i * 32) * RSB2, bptr + (size_t)i * 32 * HIDDEN + koff);
        cp_commit();
    };

    issue(0);
    issue(1);

    float accf[4][4][4];
#pragma unroll
    for (int i = 0; i < 4; i++)
#pragma unroll
        for (int j = 0; j < 4; j++)
#pragma unroll
            for (int r = 0; r < 4; r++) accf[i][j][r] = 0.0f;

    int lrow = (lane & 7) + ((lane >> 3) & 1) * 8;
    int lkb = (lane >> 4) * 16;
    uint32_t a_off = (uint32_t)(warp_m * 64 + lrow) * RSB2 + lkb;
    uint32_t b_off = (uint32_t)(128 + warp_n * 32 + lrow) * RSB2 + lkb;

#pragma unroll
    for (int kb = 0; kb < 4; kb++) {   // K=256, BK=64
        asm volatile("cp.async.wait_group 1;\n" ::: "memory");
        __syncthreads();
        if (kb + 2 < 4) issue(kb + 2);

        uint32_t smA = sb + (kb % 3) * STGH;

        uint32_t acc16[4][4][2];       // fp16 accumulators for this k-block
#pragma unroll
        for (int i = 0; i < 4; i++)
#pragma unroll
            for (int j = 0; j < 4; j++) {
                acc16[i][j][0] = 0u;
                acc16[i][j][1] = 0u;
            }

#pragma unroll
        for (int k16 = 0; k16 < 4; k16++) {
            uint32_t ko = k16 * 32;
            uint32_t ar[4][4];
#pragma unroll
            for (int fm = 0; fm < 4; fm++)
                LDSM_X4(ar[fm][0], ar[fm][1], ar[fm][2], ar[fm][3],
                        smA + a_off + fm * 16 * RSB2 + ko);
            uint32_t br[4][2];
#pragma unroll
            for (int fp = 0; fp < 2; fp++) {
                uint32_t r0, r1, r2, r3;
                LDSM_X4(r0, r1, r2, r3, smA + b_off + fp * 16 * RSB2 + ko);
                br[2 * fp][0] = r0; br[2 * fp][1] = r2;
                br[2 * fp + 1][0] = r1; br[2 * fp + 1][1] = r3;
            }
#pragma unroll
            for (int fm = 0; fm < 4; fm++)
#pragma unroll
                for (int fn = 0; fn < 4; fn++)
                    MMA_F16H(acc16[fm][fn], ar[fm], br[fn]);
        }

        // promote fp16 chunk accumulators into fp32 master
#pragma unroll
        for (int fm = 0; fm < 4; fm++)
#pragma unroll
            for (int fn = 0; fn < 4; fn++) {
                float2 p0 = __half22float2(
                    *reinterpret_cast<__half2*>(&acc16[fm][fn][0]));
                float2 p1 = __half22float2(
                    *reinterpret_cast<__half2*>(&acc16[fm][fn][1]));
                accf[fm][fn][0] += p0.x;
                accf[fm][fn][1] += p0.y;
                accf[fm][fn][2] += p1.x;
                accf[fm][fn][3] += p1.y;
            }
    }

    // epilogue
    int gr = lane >> 2;
    int qc = (lane & 3) * 2;
#pragma unroll
    for (int fm = 0; fm < 4; fm++) {
        int m0 = bm + warp_m * 64 + fm * 16 + gr;
#pragma unroll
        for (int fn = 0; fn < 4; fn++) {
            int c0 = bn + warp_n * 32 + fn * 8 + qc;
            float2 bv = *reinterpret_cast<const float2*>(bias + c0);
            *reinterpret_cast<float2*>(out + (size_t)m0 * VOCAB + c0) =
                make_float2(accf[fm][fn][0] + bv.x, accf[fm][fn][1] + bv.y);
            *reinterpret_cast<float2*>(out + (size_t)(m0 + 8) * VOCAB + c0) =
                make_float2(accf[fm][fn][2] + bv.x, accf[fm][fn][3] + bv.y);
        }
    }
}

using G1 = void(const __half*, const __half*, const float*, __half*, int);

#define SMEM_G1 (3 * (64 + 128) * RSB2)    // 82944

// ---------------------------------------------------------------------------
extern "C" void kernel_launch(void* const* d_in, const int* in_sizes, int n_in,
                              void* d_out, int out_size) {
    const int*   tokens = (const int*)  d_in[0];
    const float* emb    = (const float*)d_in[1];
    const float* W1     = (const float*)d_in[2];
    const float* b1     = (const float*)d_in[3];
    const float* W2     = (const float*)d_in[4];
    const float* b2     = (const float*)d_in[5];
    float* out = (float*)d_out;

    __half *fp, *w1t, *w2t, *hp;
    cudaGetSymbolAddress((void**)&fp,  g_flat);
    cudaGetSymbolAddress((void**)&w1t, g_w1t);
    cudaGetSymbolAddress((void**)&w2t, g_w2t);
    cudaGetSymbolAddress((void**)&hp,  g_h);

    cudaFuncSetAttribute((G1*)gemm16<K1, 64, 128, 2, 4>,
                         cudaFuncAttributeMaxDynamicSharedMemorySize, SMEM_G1);
    cudaFuncSetAttribute(gemm2h,
                         cudaFuncAttributeMaxDynamicSharedMemorySize, SMEM_G2);

    // 1) gather -> fp16 flat
    {
        int total8 = MROWS * (K1 / 8);
        gather_f16<<<(total8 + 255) / 256, 256>>>(tokens, emb);
    }
    // 2) weight transposes -> fp16 K-major
    {
        dim3 blk(32, 32);
        transpose_f16<<<dim3(HIDDEN / 32, K1 / 32), blk>>>(W1, w1t, K1, HIDDEN);
        transpose_f16<<<dim3(VOCAB / 32, HIDDEN / 32), blk>>>(W2, w2t, HIDDEN, VOCAB);
    }
    // 3) h = fp16(gelu(flat @ W1^T + b1))   (M=8192, N=256, K=1536)
    {
        dim3 grid(MROWS / 64, HIDDEN / 128);    // (128, 2)
        gemm16<K1, 64, 128, 2, 4><<<grid, 256, SMEM_G1>>>(fp, w1t, b1, hp, HIDDEN);
    }
    // 4) logits = h @ W2^T + b2   (M=8192, N=32000, K=256), fp16 accum
    {
        dim3 grid(MROWS / 128, VOCAB / 128);    // (64, 250)
        gemm2h<<<grid, 256, SMEM_G2>>>(hp, w2t, b2, out);
    }
}

// round 14
// speedup vs baseline: 1.1311x; 1.1311x over previous
#include <cuda_runtime.h>
#include <cuda_fp16.h>
#include <math.h>
#include <stdint.h>

#define SEQ    2048
#define BATCH  4
#define KCTX   3
#define EMBED  512
#define HIDDEN 256
#define VOCAB  32000
#define MROWS  (SEQ * BATCH)      // 8192
#define K1     (KCTX * EMBED)     // 1536

// ---------------- scratch (static device globals) ----------------
__device__ __half g_flat[MROWS * K1];      // [8192][1536] fp16
__device__ __half g_w1t[HIDDEN * K1];      // [256][1536] K-major fp16
__device__ __half g_w2t[VOCAB * HIDDEN];   // [32000][256] K-major fp16
__device__ __half g_h[MROWS * HIDDEN];     // [8192][256] fp16

// ---------------- helpers ----------------
__device__ __forceinline__ uint32_t smem_u32(const void* p) {
    uint32_t a;
    asm("{ .reg .u64 t; cvta.to.shared.u64 t, %1; cvt.u32.u64 %0, t; }" : "=r"(a) : "l"(p));
    return a;
}
__device__ __forceinline__ void cp16(uint32_t dst, const void* src) {
    asm volatile("cp.async.cg.shared.global [%0], [%1], 16;\n" :: "r"(dst), "l"(src));
}
__device__ __forceinline__ void cp_commit() { asm volatile("cp.async.commit_group;\n" ::: "memory"); }

#define LDSM_X4(r0, r1, r2, r3, addr) \
    asm volatile("ldmatrix.sync.aligned.m8n8.x4.shared.b16 {%0,%1,%2,%3}, [%4];" \
                 : "=r"(r0), "=r"(r1), "=r"(r2), "=r"(r3) : "r"(addr))

#define MMA_F16(d, a, b) \
    asm volatile("mma.sync.aligned.m16n8k16.row.col.f32.f16.f16.f32 " \
                 "{%0,%1,%2,%3}, {%4,%5,%6,%7}, {%8,%9}, {%0,%1,%2,%3};" \
                 : "+f"((d)[0]), "+f"((d)[1]), "+f"((d)[2]), "+f"((d)[3]) \
                 : "r"((a)[0]), "r"((a)[1]), "r"((a)[2]), "r"((a)[3]), \
                   "r"((b)[0]), "r"((b)[1]))

__device__ __forceinline__ void stcs2(float* p, float x, float y) {
    asm volatile("st.global.cs.v2.f32 [%0], {%1, %2};" :: "l"(p), "f"(x), "f"(y) : "memory");
}

__device__ __forceinline__ float gelu_exact(float x) {
    return 0.5f * x * (1.0f + erff(x * 0.70710678118654752f));
}

// ---------------------------------------------------------------------------
// Gather -> fp16 flat
// ---------------------------------------------------------------------------
__global__ void gather_f16(const int* __restrict__ tokens, const float* __restrict__ emb) {
    int idx = blockIdx.x * blockDim.x + threadIdx.x;   // one 8-elem chunk
    const int Q = K1 / 8;                               // 192 per row
    if (idx >= MROWS * Q) return;
    int r = idx / Q;
    int q = idx - r * Q;
    int s = r >> 2;
    int b = r & 3;
    int g = q / (EMBED / 8);
    int e8 = q - g * (EMBED / 8);
    int pos = s + g - (KCTX - 1);
    int tok = (pos >= 0) ? tokens[pos * BATCH + b] : 0;
    const float4* src = reinterpret_cast<const float4*>(emb + (size_t)tok * EMBED) + e8 * 2;
    float4 v0 = src[0];
    float4 v1 = src[1];
    struct alignas(16) H8 { __half2 a, b, c, d; } o;
    o.a = __floats2half2_rn(v0.x, v0.y);
    o.b = __floats2half2_rn(v0.z, v0.w);
    o.c = __floats2half2_rn(v1.x, v1.y);
    o.d = __floats2half2_rn(v1.z, v1.w);
    reinterpret_cast<H8*>(g_flat)[idx] = o;
}

// ---------------------------------------------------------------------------
// Transpose + fp16: W[R][C] -> T[C][R]
// ---------------------------------------------------------------------------
__global__ void transpose_f16(const float* __restrict__ W, __half* __restrict__ T,
                              int R, int C) {
    __shared__ float t[32][33];
    int c = blockIdx.x * 32 + threadIdx.x;
    int r = blockIdx.y * 32 + threadIdx.y;
    t[threadIdx.y][threadIdx.x] = W[(size_t)r * C + c];
    __syncthreads();
    int c2 = blockIdx.x * 32 + threadIdx.y;
    int r2 = blockIdx.y * 32 + threadIdx.x;
    T[(size_t)c2 * R + r2] = __float2half_rn(t[threadIdx.x][threadIdx.y]);
}

// ---------------------------------------------------------------------------
// GEMM1 (fp16 HMMA, fp32 accum): h = fp16(gelu(flat @ W1^T + b1))
// BM=64, BN=128, BK=64, 8 warps (2x4), warp 32x32. 3-stage cp.async.
// ---------------------------------------------------------------------------
#define RSB2 144   // 64 halves (128B) + 16B pad

template <int KD, int BMt, int BN_, int WM, int WN>
__global__ void __launch_bounds__(32 * WM * WN, 2)
gemm16(const __half* __restrict__ A, const __half* __restrict__ Bt,
       const float* __restrict__ bias, __half* __restrict__ outp, int N) {
    extern __shared__ char smem[];
    constexpr int NT    = 32 * WM * WN;
    constexpr int WROWS = BMt / WM;
    constexpr int WCOLS = BN_ / WN;
    constexpr int MFR   = WROWS / 16;
    constexpr int NFR   = WCOLS / 8;
    constexpr int ROWS  = BMt + BN_;
    constexpr int STAGE = ROWS * RSB2;
    constexpr int NKB   = KD / 64;
    constexpr int NCP   = ROWS * 8 / NT;

    uint32_t sb = smem_u32(smem);
    int tid = threadIdx.x;
    int wid = tid >> 5;
    int lane = tid & 31;
    int warp_m = wid % WM;
    int warp_n = wid / WM;
    int bm = blockIdx.x * BMt;
    int bn = blockIdx.y * BN_;

    float acc[MFR][NFR][4];
#pragma unroll
    for (int i = 0; i < MFR; i++)
#pragma unroll
        for (int j = 0; j < NFR; j++)
#pragma unroll
            for (int r = 0; r < 4; r++) acc[i][j][r] = 0.0f;

    auto issue = [&](int kb) {
        int s = kb % 3;
        int koff = kb * 64;
        uint32_t base = sb + s * STAGE;
#pragma unroll
        for (int i = 0; i < NCP; i++) {
            int li = tid + i * NT;
            int r = li >> 3;
            int ch = li & 7;
            const __half* src = (r < BMt)
                ? A  + (size_t)(bm + r) * KD + koff + ch * 8
                : Bt + (size_t)(bn + r - BMt) * KD + koff + ch * 8;
            cp16(base + r * RSB2 + ch * 16, src);
        }
        cp_commit();
    };

    issue(0);
    issue(1);

    int lrow = (lane & 7) + ((lane >> 3) & 1) * 8;
    int lkb = (lane >> 4) * 16;
    uint32_t a_off = (uint32_t)(warp_m * WROWS + lrow) * RSB2 + lkb;
    uint32_t b_off = (uint32_t)(BMt + warp_n * WCOLS + lrow) * RSB2 + lkb;

    for (int kb = 0; kb < NKB; kb++) {
        int s = kb % 3;
        asm volatile("cp.async.wait_group 1;\n" ::: "memory");
        __syncthreads();
        if (kb + 2 < NKB) issue(kb + 2);

        uint32_t smA = sb + s * STAGE;
#pragma unroll
        for (int k16 = 0; k16 < 4; k16++) {
            uint32_t ko = k16 * 32;
            uint32_t ar[MFR][4];
#pragma unroll
            for (int fm = 0; fm < MFR; fm++)
                LDSM_X4(ar[fm][0], ar[fm][1], ar[fm][2], ar[fm][3],
                        smA + a_off + fm * 16 * RSB2 + ko);
            uint32_t br[NFR][2];
#pragma unroll
            for (int fp = 0; fp < NFR / 2; fp++) {
                uint32_t r0, r1, r2, r3;
                LDSM_X4(r0, r1, r2, r3,
                        smA + b_off + fp * 16 * RSB2 + ko);
                br[2 * fp][0] = r0; br[2 * fp][1] = r2;
                br[2 * fp + 1][0] = r1; br[2 * fp + 1][1] = r3;
            }
#pragma unroll
            for (int fm = 0; fm < MFR; fm++)
#pragma unroll
                for (int fn = 0; fn < NFR; fn++)
                    MMA_F16(acc[fm][fn], ar[fm], br[fn]);
        }
    }

    int gr = lane >> 2;
    int qc = (lane & 3) * 2;
#pragma unroll
    for (int fm = 0; fm < MFR; fm++) {
        int m0 = bm + warp_m * WROWS + fm * 16 + gr;
#pragma unroll
        for (int fn = 0; fn < NFR; fn++) {
            int c0 = bn + warp_n * WCOLS + fn * 8 + qc;
            float2 bv = *reinterpret_cast<const float2*>(bias + c0);
            *reinterpret_cast<__half2*>(outp + (size_t)m0 * N + c0) =
                __floats2half2_rn(gelu_exact(acc[fm][fn][0] + bv.x),
                                  gelu_exact(acc[fm][fn][1] + bv.y));
            *reinterpret_cast<__half2*>(outp + (size_t)(m0 + 8) * N + c0) =
                __floats2half2_rn(gelu_exact(acc[fm][fn][2] + bv.x),
                                  gelu_exact(acc[fm][fn][3] + bv.y));
        }
    }
}

// ---------------------------------------------------------------------------
// GEMM2 (sync-free resident-K): logits = h @ W2^T + b2.
// M=8192, N=32000, K=256. BM=128, BN=64. 256 threads, 8 warps (4m x 2n),
// warp tile 32x32. Whole A band (128x256) + B tile (64x256) in SMEM;
// ONE load phase, ONE syncthreads, then a barrier-free MMA stream.
// 2 CTAs/SM co-resident hide each other's load phase. Streaming stores.
// ---------------------------------------------------------------------------
#define RS_A 528                         // 256 halves (512B) + 16B pad
#define SMEM_G2 ((128 + 64) * RS_A)      // 101376

__global__ void __launch_bounds__(256, 2)
gemm2r(const __half* __restrict__ A, const __half* __restrict__ Bt,
       const float* __restrict__ bias, float* __restrict__ out) {
    extern __shared__ char smem[];
    uint32_t sb = smem_u32(smem);
    int tid = threadIdx.x;
    int wid = tid >> 5;
    int lane = tid & 31;
    int warp_m = wid & 3;                // 4 (32 rows each)
    int warp_n = wid >> 2;               // 2 (32 cols each)
    int bm = blockIdx.x * 128;
    int bn = blockIdx.y * 64;

    // ---- load phase: A 128 rows + B 64 rows, 512B each ----
    int lr = tid >> 3;                   // 0..31
    int lc = tid & 7;                    // 16B chunk 0..7 (of first 128B)
    {
        const __half* aptr = A  + (size_t)(bm + lr) * HIDDEN + lc * 8;
        const __half* bptr = Bt + (size_t)(bn + lr) * HIDDEN + lc * 8;
        uint32_t ad = sb + (uint32_t)lr * RS_A + lc * 16;
        uint32_t bd = sb + (uint32_t)(128 + lr) * RS_A + lc * 16;
#pragma unroll
        for (int i = 0; i < 4; i++)      // A rows lr + 32i
#pragma unroll
            for (int j = 0; j < 4; j++)  // 128B quarters of the row
                cp16(ad + i * 32 * RS_A + j * 128,
                     aptr + (size_t)i * 32 * HIDDEN + j * 64);
#pragma unroll
        for (int i = 0; i < 2; i++)      // B rows lr + 32i
#pragma unroll
            for (int j = 0; j < 4; j++)
                cp16(bd + i * 32 * RS_A + j * 128,
                     bptr + (size_t)i * 32 * HIDDEN + j * 64);
        cp_commit();
    }
    asm volatile("cp.async.wait_group 0;\n" ::: "memory");
    __syncthreads();                     // the ONLY barrier

    // ---- barrier-free MMA stream ----
    float acc[2][4][4];
#pragma unroll
    for (int i = 0; i < 2; i++)
#pragma unroll
        for (int j = 0; j < 4; j++)
#pragma unroll
            for (int r = 0; r < 4; r++) acc[i][j][r] = 0.0f;

    int lrow = (lane & 7) + ((lane >> 3) & 1) * 8;
    int lkb = (lane >> 4) * 16;
    uint32_t a_off = sb + (uint32_t)(warp_m * 32 + lrow) * RS_A + lkb;
    uint32_t b_off = sb + (uint32_t)(128 + warp_n * 32 + lrow) * RS_A + lkb;

#pragma unroll
    for (int k16 = 0; k16 < 16; k16++) { // K=256 in one pass
        uint32_t ko = k16 * 32;          // 32B per k16 within 512B row
        uint32_t ar[2][4];
#pragma unroll
        for (int fm = 0; fm < 2; fm++)
            LDSM_X4(ar[fm][0], ar[fm][1], ar[fm][2], ar[fm][3],
                    a_off + fm * 16 * RS_A + ko);
        uint32_t br[4][2];
#pragma unroll
        for (int fp = 0; fp < 2; fp++) {
            uint32_t r0, r1, r2, r3;
            LDSM_X4(r0, r1, r2, r3, b_off + fp * 16 * RS_A + ko);
            br[2 * fp][0] = r0; br[2 * fp][1] = r2;
            br[2 * fp + 1][0] = r1; br[2 * fp + 1][1] = r3;
        }
#pragma unroll
        for (int fm = 0; fm < 2; fm++)
#pragma unroll
            for (int fn = 0; fn < 4; fn++)
                MMA_F16(acc[fm][fn], ar[fm], br[fn]);
    }

    // ---- epilogue: bias + streaming fp32 stores ----
    int gr = lane >> 2;
    int qc = (lane & 3) * 2;
#pragma unroll
    for (int fm = 0; fm < 2; fm++) {
        int m0 = bm + warp_m * 32 + fm * 16 + gr;
#pragma unroll
        for (int fn = 0; fn < 4; fn++) {
            int c0 = bn + warp_n * 32 + fn * 8 + qc;
            float2 bv = *reinterpret_cast<const float2*>(bias + c0);
            stcs2(out + (size_t)m0 * VOCAB + c0,
                  acc[fm][fn][0] + bv.x, acc[fm][fn][1] + bv.y);
            stcs2(out + (size_t)(m0 + 8) * VOCAB + c0,
                  acc[fm][fn][2] + bv.x, acc[fm][fn][3] + bv.y);
        }
    }
}

using G1 = void(const __half*, const __half*, const float*, __half*, int);

#define SMEM_G1 (3 * (64 + 128) * RSB2)    // 82944

// ---------------------------------------------------------------------------
extern "C" void kernel_launch(void* const* d_in, const int* in_sizes, int n_in,
                              void* d_out, int out_size) {
    const int*   tokens = (const int*)  d_in[0];
    const float* emb    = (const float*)d_in[1];
    const float* W1     = (const float*)d_in[2];
    const float* b1     = (const float*)d_in[3];
    const float* W2     = (const float*)d_in[4];
    const float* b2     = (const float*)d_in[5];
    float* out = (float*)d_out;

    __half *fp, *w1t, *w2t, *hp;
    cudaGetSymbolAddress((void**)&fp,  g_flat);
    cudaGetSymbolAddress((void**)&w1t, g_w1t);
    cudaGetSymbolAddress((void**)&w2t, g_w2t);
    cudaGetSymbolAddress((void**)&hp,  g_h);

    cudaFuncSetAttribute((G1*)gemm16<K1, 64, 128, 2, 4>,
                         cudaFuncAttributeMaxDynamicSharedMemorySize, SMEM_G1);
    cudaFuncSetAttribute(gemm2r,
                         cudaFuncAttributeMaxDynamicSharedMemorySize, SMEM_G2);

    // 1) gather -> fp16 flat
    {
        int total8 = MROWS * (K1 / 8);
        gather_f16<<<(total8 + 255) / 256, 256>>>(tokens, emb);
    }
    // 2) weight transposes -> fp16 K-major
    {
        dim3 blk(32, 32);
        transpose_f16<<<dim3(HIDDEN / 32, K1 / 32), blk>>>(W1, w1t, K1, HIDDEN);
        transpose_f16<<<dim3(VOCAB / 32, HIDDEN / 32), blk>>>(W2, w2t, HIDDEN, VOCAB);
    }
    // 3) h = fp16(gelu(flat @ W1^T + b1))   (M=8192, N=256, K=1536)
    {
        dim3 grid(MROWS / 64, HIDDEN / 128);    // (128, 2)
        gemm16<K1, 64, 128, 2, 4><<<grid, 256, SMEM_G1>>>(fp, w1t, b1, hp, HIDDEN);
    }
    // 4) logits = h @ W2^T + b2   (M=8192, N=32000, K=256), sync-free resident-K
    {
        dim3 grid(MROWS / 128, VOCAB / 64);     // (64, 500)
        gemm2r<<<grid, 256, SMEM_G2>>>(hp, w2t, b2, out);
    }
}

// round 16
// speedup vs baseline: 1.1492x; 1.0160x over previous
#include <cuda_runtime.h>
#include <cuda_fp16.h>
#include <math.h>
#include <stdint.h>

#define SEQ    2048
#define BATCH  4
#define KCTX   3
#define EMBED  512
#define HIDDEN 256
#define VOCAB  32000
#define MROWS  (SEQ * BATCH)      // 8192
#define K1     (KCTX * EMBED)     // 1536

// ---------------- scratch (static device globals) ----------------
__device__ __half g_flat[MROWS * K1];      // [8192][1536] fp16
__device__ __half g_w1t[HIDDEN * K1];      // [256][1536] K-major fp16
__device__ __half g_w2t[VOCAB * HIDDEN];   // [32000][256] K-major fp16
__device__ __half g_h[MROWS * HIDDEN];     // [8192][256] fp16

// ---------------- helpers ----------------
__device__ __forceinline__ uint32_t smem_u32(const void* p) {
    uint32_t a;
    asm("{ .reg .u64 t; cvta.to.shared.u64 t, %1; cvt.u32.u64 %0, t; }" : "=r"(a) : "l"(p));
    return a;
}
__device__ __forceinline__ void cp16(uint32_t dst, const void* src) {
    asm volatile("cp.async.cg.shared.global [%0], [%1], 16;\n" :: "r"(dst), "l"(src));
}
__device__ __forceinline__ void cp_commit() { asm volatile("cp.async.commit_group;\n" ::: "memory"); }

#define LDSM_X4(r0, r1, r2, r3, addr) \
    asm volatile("ldmatrix.sync.aligned.m8n8.x4.shared.b16 {%0,%1,%2,%3}, [%4];" \
                 : "=r"(r0), "=r"(r1), "=r"(r2), "=r"(r3) : "r"(addr))

#define MMA_F16(d, a, b) \
    asm volatile("mma.sync.aligned.m16n8k16.row.col.f32.f16.f16.f32 " \
                 "{%0,%1,%2,%3}, {%4,%5,%6,%7}, {%8,%9}, {%0,%1,%2,%3};" \
                 : "+f"((d)[0]), "+f"((d)[1]), "+f"((d)[2]), "+f"((d)[3]) \
                 : "r"((a)[0]), "r"((a)[1]), "r"((a)[2]), "r"((a)[3]), \
                   "r"((b)[0]), "r"((b)[1]))

__device__ __forceinline__ float gelu_exact(float x) {
    return 0.5f * x * (1.0f + erff(x * 0.70710678118654752f));
}

// ---------------------------------------------------------------------------
// Gather -> fp16 flat
// ---------------------------------------------------------------------------
__global__ void gather_f16(const int* __restrict__ tokens, const float* __restrict__ emb) {
    int idx = blockIdx.x * blockDim.x + threadIdx.x;   // one 8-elem chunk
    const int Q = K1 / 8;                               // 192 per row
    if (idx >= MROWS * Q) return;
    int r = idx / Q;
    int q = idx - r * Q;
    int s = r >> 2;
    int b = r & 3;
    int g = q / (EMBED / 8);
    int e8 = q - g * (EMBED / 8);
    int pos = s + g - (KCTX - 1);
    int tok = (pos >= 0) ? tokens[pos * BATCH + b] : 0;
    const float4* src = reinterpret_cast<const float4*>(emb + (size_t)tok * EMBED) + e8 * 2;
    float4 v0 = src[0];
    float4 v1 = src[1];
    struct alignas(16) H8 { __half2 a, b, c, d; } o;
    o.a = __floats2half2_rn(v0.x, v0.y);
    o.b = __floats2half2_rn(v0.z, v0.w);
    o.c = __floats2half2_rn(v1.x, v1.y);
    o.d = __floats2half2_rn(v1.z, v1.w);
    reinterpret_cast<H8*>(g_flat)[idx] = o;
}

// ---------------------------------------------------------------------------
// Merged transpose + fp16 for W1 and W2 in ONE launch.
// Linear 32x32-tile blocks: first NB1 blocks handle W1 [1536][256],
// the rest handle W2 [256][32000]. Output K-major ([C][R]).
// ---------------------------------------------------------------------------
#define NB1X (HIDDEN / 32)   // 8
#define NB1Y (K1 / 32)       // 48
#define NB1  (NB1X * NB1Y)   // 384
#define NB2X (VOCAB / 32)    // 1000
#define NB2Y (HIDDEN / 32)   // 8
#define NB2  (NB2X * NB2Y)   // 8000

__global__ void transpose_both(const float* __restrict__ W1, const float* __restrict__ W2) {
    __shared__ float t[32][33];
    int blk = blockIdx.x;
    const float* W;
    __half* T;
    int bx, by, R, C;
    if (blk < NB1) {
        W = W1; T = g_w1t; R = K1; C = HIDDEN;
        bx = blk % NB1X; by = blk / NB1X;
    } else {
        int b2 = blk - NB1;
        W = W2; T = g_w2t; R = HIDDEN; C = VOCAB;
        bx = b2 % NB2X; by = b2 / NB2X;
    }
    int c = bx * 32 + threadIdx.x;
    int r = by * 32 + threadIdx.y;
    t[threadIdx.y][threadIdx.x] = W[(size_t)r * C + c];
    __syncthreads();
    int c2 = bx * 32 + threadIdx.y;
    int r2 = by * 32 + threadIdx.x;
    T[(size_t)c2 * R + r2] = __float2half_rn(t[threadIdx.x][threadIdx.y]);
}

// ---------------------------------------------------------------------------
// Unified fp16 HMMA GEMM: C[M,N] = A[M,K] @ B[N,K]^T (+bias, opt GELU)
// BK=64, 144B-stride smem rows, 3-stage cp.async, minBlocks=2.
// EPI=0: out fp32 = acc + bias.    EPI=1: out fp16 = gelu(acc + bias).
// ---------------------------------------------------------------------------
#define RSB2 144   // 64 halves (128B) + 16B pad

template <int KD, int BMt, int BN_, int WM, int WN, int EPI>
__global__ void __launch_bounds__(32 * WM * WN, 2)
gemm16(const __half* __restrict__ A, const __half* __restrict__ Bt,
       const float* __restrict__ bias, void* __restrict__ outp, int N) {
    extern __shared__ char smem[];
    constexpr int NT    = 32 * WM * WN;
    constexpr int WROWS = BMt / WM;
    constexpr int WCOLS = BN_ / WN;
    constexpr int MFR   = WROWS / 16;
    constexpr int NFR   = WCOLS / 8;
    constexpr int ROWS  = BMt + BN_;
    constexpr int STAGE = ROWS * RSB2;
    constexpr int NKB   = KD / 64;
    constexpr int NCP   = ROWS * 8 / NT;

    uint32_t sb = smem_u32(smem);
    int tid = threadIdx.x;
    int wid = tid >> 5;
    int lane = tid & 31;
    int warp_m = wid % WM;
    int warp_n = wid / WM;
    int bm = blockIdx.x * BMt;
    int bn = blockIdx.y * BN_;

    float acc[MFR][NFR][4];
#pragma unroll
    for (int i = 0; i < MFR; i++)
#pragma unroll
        for (int j = 0; j < NFR; j++)
#pragma unroll
            for (int r = 0; r < 4; r++) acc[i][j][r] = 0.0f;

    auto issue = [&](int kb) {
        int s = kb % 3;
        int koff = kb * 64;
        uint32_t base = sb + s * STAGE;
#pragma unroll
        for (int i = 0; i < NCP; i++) {
            int li = tid + i * NT;
            int r = li >> 3;
            int ch = li & 7;
            const __half* src = (r < BMt)
                ? A  + (size_t)(bm + r) * KD + koff + ch * 8
                : Bt + (size_t)(bn + r - BMt) * KD + koff + ch * 8;
            cp16(base + r * RSB2 + ch * 16, src);
        }
        cp_commit();
    };

    issue(0);
    issue(1);

    int lrow = (lane & 7) + ((lane >> 3) & 1) * 8;
    int lkb = (lane >> 4) * 16;
    uint32_t a_off = (uint32_t)(warp_m * WROWS + lrow) * RSB2 + lkb;
    uint32_t b_off = (uint32_t)(BMt + warp_n * WCOLS + lrow) * RSB2 + lkb;

    for (int kb = 0; kb < NKB; kb++) {
        int s = kb % 3;
        asm volatile("cp.async.wait_group 1;\n" ::: "memory");
        __syncthreads();
        if (kb + 2 < NKB) issue(kb + 2);

        uint32_t smA = sb + s * STAGE;
#pragma unroll
        for (int k16 = 0; k16 < 4; k16++) {
            uint32_t ko = k16 * 32;
            uint32_t ar[MFR][4];
#pragma unroll
            for (int fm = 0; fm < MFR; fm++)
                LDSM_X4(ar[fm][0], ar[fm][1], ar[fm][2], ar[fm][3],
                        smA + a_off + fm * 16 * RSB2 + ko);
            uint32_t br[NFR][2];
#pragma unroll
            for (int fp = 0; fp < NFR / 2; fp++) {
                uint32_t r0, r1, r2, r3;
                LDSM_X4(r0, r1, r2, r3,
                        smA + b_off + fp * 16 * RSB2 + ko);
                br[2 * fp][0] = r0; br[2 * fp][1] = r2;
                br[2 * fp + 1][0] = r1; br[2 * fp + 1][1] = r3;
            }
#pragma unroll
            for (int fm = 0; fm < MFR; fm++)
#pragma unroll
                for (int fn = 0; fn < NFR; fn++)
                    MMA_F16(acc[fm][fn], ar[fm], br[fn]);
        }
    }

    // ---------------- epilogue ----------------
    int gr = lane >> 2;
    int qc = (lane & 3) * 2;
#pragma unroll
    for (int fm = 0; fm < MFR; fm++) {
        int m0 = bm + warp_m * WROWS + fm * 16 + gr;
#pragma unroll
        for (int fn = 0; fn < NFR; fn++) {
            int c0 = bn + warp_n * WCOLS + fn * 8 + qc;
            float2 bv = *reinterpret_cast<const float2*>(bias + c0);
            float v00 = acc[fm][fn][0] + bv.x;
            float v01 = acc[fm][fn][1] + bv.y;
            float v10 = acc[fm][fn][2] + bv.x;
            float v11 = acc[fm][fn][3] + bv.y;
            if (EPI == 0) {
                float* out = (float*)outp;
                *reinterpret_cast<float2*>(out + (size_t)m0 * N + c0) =
                    make_float2(v00, v01);
                *reinterpret_cast<float2*>(out + (size_t)(m0 + 8) * N + c0) =
                    make_float2(v10, v11);
            } else {
                __half* out = (__half*)outp;
                *reinterpret_cast<__half2*>(out + (size_t)m0 * N + c0) =
                    __floats2half2_rn(gelu_exact(v00), gelu_exact(v01));
                *reinterpret_cast<__half2*>(out + (size_t)(m0 + 8) * N + c0) =
                    __floats2half2_rn(gelu_exact(v10), gelu_exact(v11));
            }
        }
    }
}

using G1 = void(const __half*, const __half*, const float*, void*, int);

#define SMEM_G1 (3 * (64 + 128) * RSB2)    // 82944
#define SMEM_G2 (3 * (128 + 128) * RSB2)   // 110592

// ---------------------------------------------------------------------------
extern "C" void kernel_launch(void* const* d_in, const int* in_sizes, int n_in,
                              void* d_out, int out_size) {
    const int*   tokens = (const int*)  d_in[0];
    const float* emb    = (const float*)d_in[1];
    const float* W1     = (const float*)d_in[2];
    const float* b1     = (const float*)d_in[3];
    const float* W2     = (const float*)d_in[4];
    const float* b2     = (const float*)d_in[5];
    float* out = (float*)d_out;

    __half *fp, *w1t, *w2t, *hp;
    cudaGetSymbolAddress((void**)&fp,  g_flat);
    cudaGetSymbolAddress((void**)&w1t, g_w1t);
    cudaGetSymbolAddress((void**)&w2t, g_w2t);
    cudaGetSymbolAddress((void**)&hp,  g_h);

    cudaFuncSetAttribute((G1*)gemm16<K1, 64, 128, 2, 4, 1>,
                         cudaFuncAttributeMaxDynamicSharedMemorySize, SMEM_G1);
    cudaFuncSetAttribute((G1*)gemm16<HIDDEN, 128, 128, 2, 4, 0>,
                         cudaFuncAttributeMaxDynamicSharedMemorySize, SMEM_G2);

    // 1) gather -> fp16 flat
    {
        int total8 = MROWS * (K1 / 8);
        gather_f16<<<(total8 + 255) / 256, 256>>>(tokens, emb);
    }
    // 2) both weight transposes -> fp16 K-major, single launch
    {
        dim3 blk(32, 32);
        transpose_both<<<NB1 + NB2, blk>>>(W1, W2);
    }
    // 3) h = fp16(gelu(flat @ W1^T + b1))   (M=8192, N=256, K=1536)
    {
        dim3 grid(MROWS / 64, HIDDEN / 128);    // (128, 2)
        gemm16<K1, 64, 128, 2, 4, 1><<<grid, 256, SMEM_G1>>>(fp, w1t, b1, hp, HIDDEN);
    }
    // 4) logits = h @ W2^T + b2   (M=8192, N=32000, K=256)
    {
        dim3 grid(MROWS / 128, VOCAB / 128);    // (64, 250)
        gemm16<HIDDEN, 128, 128, 2, 4, 0><<<grid, 256, SMEM_G2>>>(hp, w2t, b2, out, VOCAB);
    }
}

// round 17
// speedup vs baseline: 1.2640x; 1.0999x over previous
#include <cuda_runtime.h>
#include <cuda_fp16.h>
#include <math.h>
#include <stdint.h>

#define SEQ    2048
#define BATCH  4
#define KCTX   3
#define EMBED  512
#define HIDDEN 256
#define VOCAB  32000
#define MROWS  (SEQ * BATCH)      // 8192
#define K1     (KCTX * EMBED)     // 1536

// ---------------- scratch (static device globals) ----------------
__device__ __half g_flat[MROWS * K1];      // [8192][1536] fp16
__device__ __half g_w1t[HIDDEN * K1];      // [256][1536] K-major fp16
__device__ __half g_w2t[VOCAB * HIDDEN];   // [32000][256] K-major fp16
__device__ __half g_h[MROWS * HIDDEN];     // [8192][256] fp16

// ---------------- helpers ----------------
__device__ __forceinline__ uint32_t smem_u32(const void* p) {
    uint32_t a;
    asm("{ .reg .u64 t; cvta.to.shared.u64 t, %1; cvt.u32.u64 %0, t; }" : "=r"(a) : "l"(p));
    return a;
}
__device__ __forceinline__ void cp16(uint32_t dst, const void* src) {
    asm volatile("cp.async.cg.shared.global [%0], [%1], 16;\n" :: "r"(dst), "l"(src));
}
__device__ __forceinline__ void cp_commit() { asm volatile("cp.async.commit_group;\n" ::: "memory"); }

#define LDSM_X4(r0, r1, r2, r3, addr) \
    asm volatile("ldmatrix.sync.aligned.m8n8.x4.shared.b16 {%0,%1,%2,%3}, [%4];" \
                 : "=r"(r0), "=r"(r1), "=r"(r2), "=r"(r3) : "r"(addr))

#define MMA_F16(d, a, b) \
    asm volatile("mma.sync.aligned.m16n8k16.row.col.f32.f16.f16.f32 " \
                 "{%0,%1,%2,%3}, {%4,%5,%6,%7}, {%8,%9}, {%0,%1,%2,%3};" \
                 : "+f"((d)[0]), "+f"((d)[1]), "+f"((d)[2]), "+f"((d)[3]) \
                 : "r"((a)[0]), "r"((a)[1]), "r"((a)[2]), "r"((a)[3]), \
                   "r"((b)[0]), "r"((b)[1]))

__device__ __forceinline__ float gelu_exact(float x) {
    return 0.5f * x * (1.0f + erff(x * 0.70710678118654752f));
}

// ---------------------------------------------------------------------------
// Gather -> fp16 flat
// ---------------------------------------------------------------------------
__global__ void gather_f16(const int* __restrict__ tokens, const float* __restrict__ emb) {
    int idx = blockIdx.x * blockDim.x + threadIdx.x;   // one 8-elem chunk
    const int Q = K1 / 8;                               // 192 per row
    if (idx >= MROWS * Q) return;
    int r = idx / Q;
    int q = idx - r * Q;
    int s = r >> 2;
    int b = r & 3;
    int g = q / (EMBED / 8);
    int e8 = q - g * (EMBED / 8);
    int pos = s + g - (KCTX - 1);
    int tok = (pos >= 0) ? tokens[pos * BATCH + b] : 0;
    const float4* src = reinterpret_cast<const float4*>(emb + (size_t)tok * EMBED) + e8 * 2;
    float4 v0 = src[0];
    float4 v1 = src[1];
    struct alignas(16) H8 { __half2 a, b, c, d; } o;
    o.a = __floats2half2_rn(v0.x, v0.y);
    o.b = __floats2half2_rn(v0.z, v0.w);
    o.c = __floats2half2_rn(v1.x, v1.y);
    o.d = __floats2half2_rn(v1.z, v1.w);
    reinterpret_cast<H8*>(g_flat)[idx] = o;
}

// ---------------------------------------------------------------------------
// Merged transpose + fp16 for W1 and W2 in ONE launch.
// ---------------------------------------------------------------------------
#define NB1X (HIDDEN / 32)   // 8
#define NB1Y (K1 / 32)       // 48
#define NB1  (NB1X * NB1Y)   // 384
#define NB2X (VOCAB / 32)    // 1000
#define NB2Y (HIDDEN / 32)   // 8
#define NB2  (NB2X * NB2Y)   // 8000

__global__ void transpose_both(const float* __restrict__ W1, const float* __restrict__ W2) {
    __shared__ float t[32][33];
    int blk = blockIdx.x;
    const float* W;
    __half* T;
    int bx, by, R, C;
    if (blk < NB1) {
        W = W1; T = g_w1t; R = K1; C = HIDDEN;
        bx = blk % NB1X; by = blk / NB1X;
    } else {
        int b2 = blk - NB1;
        W = W2; T = g_w2t; R = HIDDEN; C = VOCAB;
        bx = b2 % NB2X; by = b2 / NB2X;
    }
    int c = bx * 32 + threadIdx.x;
    int r = by * 32 + threadIdx.y;
    t[threadIdx.y][threadIdx.x] = W[(size_t)r * C + c];
    __syncthreads();
    int c2 = bx * 32 + threadIdx.y;
    int r2 = by * 32 + threadIdx.x;
    T[(size_t)c2 * R + r2] = __float2half_rn(t[threadIdx.x][threadIdx.y]);
}

// ---------------------------------------------------------------------------
// Unified fp16 HMMA GEMM: C[M,N] = A[M,K] @ B[N,K]^T (+bias, opt GELU)
// BK=64, 144B-stride smem rows, 3-stage cp.async, minBlocks=2.
// EPI=0: out fp32 = acc + bias.    EPI=1: out fp16 = gelu(acc + bias).
// ---------------------------------------------------------------------------
#define RSB2 144   // 64 halves (128B) + 16B pad

template <int KD, int BMt, int BN_, int WM, int WN, int EPI>
__global__ void __launch_bounds__(32 * WM * WN, 2)
gemm16(const __half* __restrict__ A, const __half* __restrict__ Bt,
       const float* __restrict__ bias, void* __restrict__ outp, int N) {
    extern __shared__ char smem[];
    constexpr int NT    = 32 * WM * WN;
    constexpr int WROWS = BMt / WM;
    constexpr int WCOLS = BN_ / WN;
    constexpr int MFR   = WROWS / 16;
    constexpr int NFR   = WCOLS / 8;
    constexpr int ROWS  = BMt + BN_;
    constexpr int STAGE = ROWS * RSB2;
    constexpr int NKB   = KD / 64;
    constexpr int NCP   = ROWS * 8 / NT;

    uint32_t sb = smem_u32(smem);
    int tid = threadIdx.x;
    int wid = tid >> 5;
    int lane = tid & 31;
    int warp_m = wid % WM;
    int warp_n = wid / WM;
    int bm = blockIdx.x * BMt;
    int bn = blockIdx.y * BN_;

    float acc[MFR][NFR][4];
#pragma unroll
    for (int i = 0; i < MFR; i++)
#pragma unroll
        for (int j = 0; j < NFR; j++)
#pragma unroll
            for (int r = 0; r < 4; r++) acc[i][j][r] = 0.0f;

    auto issue = [&](int kb) {
        int s = kb % 3;
        int koff = kb * 64;
        uint32_t base = sb + s * STAGE;
#pragma unroll
        for (int i = 0; i < NCP; i++) {
            int li = tid + i * NT;
            int r = li >> 3;
            int ch = li & 7;
            const __half* src = (r < BMt)
                ? A  + (size_t)(bm + r) * KD + koff + ch * 8
                : Bt + (size_t)(bn + r - BMt) * KD + koff + ch * 8;
            cp16(base + r * RSB2 + ch * 16, src);
        }
        cp_commit();
    };

    issue(0);
    issue(1);

    int lrow = (lane & 7) + ((lane >> 3) & 1) * 8;
    int lkb = (lane >> 4) * 16;
    uint32_t a_off = (uint32_t)(warp_m * WROWS + lrow) * RSB2 + lkb;
    uint32_t b_off = (uint32_t)(BMt + warp_n * WCOLS + lrow) * RSB2 + lkb;

    for (int kb = 0; kb < NKB; kb++) {
        int s = kb % 3;
        asm volatile("cp.async.wait_group 1;\n" ::: "memory");
        __syncthreads();
        if (kb + 2 < NKB) issue(kb + 2);

        uint32_t smA = sb + s * STAGE;
#pragma unroll
        for (int k16 = 0; k16 < 4; k16++) {
            uint32_t ko = k16 * 32;
            uint32_t ar[MFR][4];
#pragma unroll
            for (int fm = 0; fm < MFR; fm++)
                LDSM_X4(ar[fm][0], ar[fm][1], ar[fm][2], ar[fm][3],
                        smA + a_off + fm * 16 * RSB2 + ko);
            uint32_t br[NFR][2];
#pragma unroll
            for (int fp = 0; fp < NFR / 2; fp++) {
                uint32_t r0, r1, r2, r3;
                LDSM_X4(r0, r1, r2, r3,
                        smA + b_off + fp * 16 * RSB2 + ko);
                br[2 * fp][0] = r0; br[2 * fp][1] = r2;
                br[2 * fp + 1][0] = r1; br[2 * fp + 1][1] = r3;
            }
#pragma unroll
            for (int fm = 0; fm < MFR; fm++)
#pragma unroll
                for (int fn = 0; fn < NFR; fn++)
                    MMA_F16(acc[fm][fn], ar[fm], br[fn]);
        }
    }

    // ---------------- epilogue ----------------
    int gr = lane >> 2;
    int qc = (lane & 3) * 2;
#pragma unroll
    for (int fm = 0; fm < MFR; fm++) {
        int m0 = bm + warp_m * WROWS + fm * 16 + gr;
#pragma unroll
        for (int fn = 0; fn < NFR; fn++) {
            int c0 = bn + warp_n * WCOLS + fn * 8 + qc;
            float2 bv = *reinterpret_cast<const float2*>(bias + c0);
            float v00 = acc[fm][fn][0] + bv.x;
            float v01 = acc[fm][fn][1] + bv.y;
            float v10 = acc[fm][fn][2] + bv.x;
            float v11 = acc[fm][fn][3] + bv.y;
            if (EPI == 0) {
                float* out = (float*)outp;
                *reinterpret_cast<float2*>(out + (size_t)m0 * N + c0) =
                    make_float2(v00, v01);
                *reinterpret_cast<float2*>(out + (size_t)(m0 + 8) * N + c0) =
                    make_float2(v10, v11);
            } else {
                __half* out = (__half*)outp;
                *reinterpret_cast<__half2*>(out + (size_t)m0 * N + c0) =
                    __floats2half2_rn(gelu_exact(v00), gelu_exact(v01));
                *reinterpret_cast<__half2*>(out + (size_t)(m0 + 8) * N + c0) =
                    __floats2half2_rn(gelu_exact(v10), gelu_exact(v11));
            }
        }
    }
}

using G1 = void(const __half*, const __half*, const float*, void*, int);

#define SMEM_G1 (3 * (64 + 128) * RSB2)    // 82944
#define SMEM_G2 (3 * (128 + 128) * RSB2)   // 110592

// ---------------------------------------------------------------------------
extern "C" void kernel_launch(void* const* d_in, const int* in_sizes, int n_in,
                              void* d_out, int out_size) {
    const int*   tokens = (const int*)  d_in[0];
    const float* emb    = (const float*)d_in[1];
    const float* W1     = (const float*)d_in[2];
    const float* b1     = (const float*)d_in[3];
    const float* W2     = (const float*)d_in[4];
    const float* b2     = (const float*)d_in[5];
    float* out = (float*)d_out;

    __half *fp, *w1t, *w2t, *hp;
    cudaGetSymbolAddress((void**)&fp,  g_flat);
    cudaGetSymbolAddress((void**)&w1t, g_w1t);
    cudaGetSymbolAddress((void**)&w2t, g_w2t);
    cudaGetSymbolAddress((void**)&hp,  g_h);

    cudaFuncSetAttribute((G1*)gemm16<K1, 64, 128, 2, 4, 1>,
                         cudaFuncAttributeMaxDynamicSharedMemorySize, SMEM_G1);
    cudaFuncSetAttribute((G1*)gemm16<HIDDEN, 128, 128, 4, 4, 0>,
                         cudaFuncAttributeMaxDynamicSharedMemorySize, SMEM_G2);

    // 1) gather -> fp16 flat
    {
        int total8 = MROWS * (K1 / 8);
        gather_f16<<<(total8 + 255) / 256, 256>>>(tokens, emb);
    }
    // 2) both weight transposes -> fp16 K-major, single launch
    {
        dim3 blk(32, 32);
        transpose_both<<<NB1 + NB2, blk>>>(W1, W2);
    }
    // 3) h = fp16(gelu(flat @ W1^T + b1))   (M=8192, N=256, K=1536)
    {
        dim3 grid(MROWS / 64, HIDDEN / 128);    // (128, 2)
        gemm16<K1, 64, 128, 2, 4, 1><<<grid, 256, SMEM_G1>>>(fp, w1t, b1, hp, HIDDEN);
    }
    // 4) logits = h @ W2^T + b2   (M=8192, N=32000, K=256)
    //    16 warps (4x4), warp tile 32x32, 512 threads, 2 CTAs/SM -> 32 warps/SM
    {
        dim3 grid(MROWS / 128, VOCAB / 128);    // (64, 250)
        gemm16<HIDDEN, 128, 128, 4, 4, 0><<<grid, 512, SMEM_G2>>>(hp, w2t, b2, out, VOCAB);
    }
}